// round 7
// baseline (speedup 1.0000x reference)
#include <cuda_runtime.h>
#include <cstdint>
#include <math.h>

// Problem dims
#define TT 128
#define NN 64
#define DD 512
#define HH 512
#define G3 1536   // 3*H

typedef unsigned long long ull;

// ---------------- packed f32x2 helpers ----------------
__device__ __forceinline__ ull fma2(ull a, ull b, ull c) {
    ull d;
    asm("fma.rn.f32x2 %0, %1, %2, %3;" : "=l"(d) : "l"(a), "l"(b), "l"(c));
    return d;
}
__device__ __forceinline__ float lo32(ull v) { return __uint_as_float((unsigned)(v & 0xffffffffu)); }
__device__ __forceinline__ float hi32(ull v) { return __uint_as_float((unsigned)(v >> 32)); }
__device__ __forceinline__ ull pack2(float x, float y) {
    return (((ull)__float_as_uint(y)) << 32) | (ull)__float_as_uint(x);
}

// ---------------- global scratch ----------------
// gi stored [m][g]: g_gi[m * 1536 + g]
__device__ float g_gi[(size_t)TT * NN * G3];

struct __align__(128) PadU { unsigned v; unsigned pad[31]; };
__device__ PadU g_cnt[4];   // one accumulating counter per row-group

// =====================================================================
// Kernel 1: gi[m, g] = sum_k x[m,k] * w_ih[g,k] + b_ih[g]
// Tiles 128(m) x 64(g), BK=32, 256 threads, 8x4 f2 thread tile,
// register double-buffered global->smem pipeline.
// =====================================================================
__global__ void __launch_bounds__(256, 2) gemm_gi_kernel(
    const float* __restrict__ x,
    const float* __restrict__ w_ih,
    const float* __restrict__ b_ih)
{
    if (blockIdx.x == 0 && blockIdx.y == 0 && threadIdx.x < 4)
        g_cnt[threadIdx.x].v = 0;

    __shared__ ull Ms[128 * 17];   // x rows (m)
    __shared__ ull Gs[64 * 17];    // w_ih rows (g)

    const int tid = threadIdx.x;
    const int g0 = blockIdx.x * 64;
    const int m0 = blockIdx.y * 128;
    const int tx = tid & 15;      // -> g group
    const int ty = tid >> 4;      // -> m group

    // staging reg addresses (fixed per thread)
    int mrow[4], mkq[4], grow[2], gkq[2];
#pragma unroll
    for (int i = 0; i < 4; i++) {
        int s = tid + i * 256;
        mrow[i] = s >> 3; mkq[i] = s & 7;
    }
#pragma unroll
    for (int i = 0; i < 2; i++) {
        int s = tid + i * 256;
        grow[i] = s >> 3; gkq[i] = s & 7;
    }

    ull acc[8][4];
#pragma unroll
    for (int i = 0; i < 8; i++)
#pragma unroll
        for (int j = 0; j < 4; j++) acc[i][j] = 0ull;

    float4 xm[4], xg[2];
#pragma unroll
    for (int i = 0; i < 4; i++)
        xm[i] = *reinterpret_cast<const float4*>(&x[(size_t)(m0 + mrow[i]) * DD + mkq[i] * 4]);
#pragma unroll
    for (int i = 0; i < 2; i++)
        xg[i] = *reinterpret_cast<const float4*>(&w_ih[(size_t)(g0 + grow[i]) * DD + gkq[i] * 4]);

    for (int k0 = 0; k0 < DD; k0 += 32) {
        // STS current tile
#pragma unroll
        for (int i = 0; i < 4; i++) {
            Ms[mrow[i] * 17 + mkq[i] * 2]     = pack2(xm[i].x, xm[i].y);
            Ms[mrow[i] * 17 + mkq[i] * 2 + 1] = pack2(xm[i].z, xm[i].w);
        }
#pragma unroll
        for (int i = 0; i < 2; i++) {
            Gs[grow[i] * 17 + gkq[i] * 2]     = pack2(xg[i].x, xg[i].y);
            Gs[grow[i] * 17 + gkq[i] * 2 + 1] = pack2(xg[i].z, xg[i].w);
        }
        __syncthreads();

        // prefetch next tile into regs (hidden behind compute)
        if (k0 + 32 < DD) {
            int kn = k0 + 32;
#pragma unroll
            for (int i = 0; i < 4; i++)
                xm[i] = *reinterpret_cast<const float4*>(&x[(size_t)(m0 + mrow[i]) * DD + kn + mkq[i] * 4]);
#pragma unroll
            for (int i = 0; i < 2; i++)
                xg[i] = *reinterpret_cast<const float4*>(&w_ih[(size_t)(g0 + grow[i]) * DD + kn + gkq[i] * 4]);
        }

#pragma unroll
        for (int kk = 0; kk < 16; kk++) {
            ull a[8], b[4];
#pragma unroll
            for (int i = 0; i < 8; i++) a[i] = Ms[(ty + 16 * i) * 17 + kk];
#pragma unroll
            for (int j = 0; j < 4; j++) b[j] = Gs[(tx + 16 * j) * 17 + kk];
#pragma unroll
            for (int i = 0; i < 8; i++)
#pragma unroll
                for (int j = 0; j < 4; j++)
                    acc[i][j] = fma2(a[i], b[j], acc[i][j]);
        }
        __syncthreads();
    }

    float bias[4];
#pragma unroll
    for (int j = 0; j < 4; j++) bias[j] = b_ih[g0 + tx + 16 * j];
#pragma unroll
    for (int i = 0; i < 8; i++) {
        int m = m0 + ty + 16 * i;
#pragma unroll
        for (int j = 0; j < 4; j++) {
            int g = g0 + tx + 16 * j;
            g_gi[(size_t)m * G3 + g] = lo32(acc[i][j]) + hi32(acc[i][j]) + bias[j];
        }
    }
}

// =====================================================================
// Kernel 2: persistent GRU scan, 128 CTAs x 512 threads.
// 4 row-groups (rb, 16 rows) x 32 dim-CTAs (jb, 16 dims).
// tid = ks*32 + pos: ks = K slice (0..15), pos = dg*4 + rg.
// h read DIRECTLY from global (t-unique addresses -> L1-safe),
// double-buffered one kk-iter ahead. w_hh in smem, bank-swizzled.
// Thread tile: 4 rows (rg+4i) x [2 dims x 3 gates] = 24 f2 acc.
// =====================================================================
#define WS_STRIDE 516   // floats; +4 swizzle when (lrow & 8)
#define RS_STRIDE 530

__global__ void __launch_bounds__(512, 1) gru_scan_kernel(
    const float* __restrict__ hxs,
    const float* __restrict__ masks,
    const float* __restrict__ w_hh,
    const float* __restrict__ b_hh,
    float* __restrict__ out)
{
    extern __shared__ float smem[];
    float* ws  = smem;                       // [48][516] + swizzle pad
    float* red = smem + 48 * WS_STRIDE + 4;  // [24][530]

    const int tid = threadIdx.x;
    const int jb = blockIdx.x & 31;       // 16 dims: jb*16 ..
    const int rb = blockIdx.x >> 5;       // 16 rows: rb*16 ..
    const int n0 = rb * 16;
    const int ks = tid >> 5;              // 0..15
    const int pos = tid & 31;
    const int rg = pos & 3;               // row in group of 4
    const int dg = pos >> 2;              // 0..7 dim pair

    // epilogue mapping (threads 0..255): 1 output each (16 rows x 16 dims)
    const int e_dim  = tid & 15;
    const int e_rloc = tid >> 4;              // valid for tid < 256
    const int e_dimg = jb * 16 + e_dim;
    const int e_i  = (e_rloc >> 2) & 3;
    const int e_rg = e_rloc & 3;
    const int e_dg = e_dim >> 1;
    const int e_dd = e_dim & 1;
    const int e_pcol = e_dg * 4 + e_rg;

    // ---- stage w_hh slice once: 48 rows (g*16+dloc) x 512, bank-swizzled ----
#pragma unroll
    for (int i = 0; i < 12; i++) {
        int s = tid + i * 512;        // 48 rows x 128 float4
        int lrow = s >> 7;            // 0..47
        int kq = s & 127;
        int g = lrow >> 4;
        int dloc = lrow & 15;
        int sw = (lrow & 8) ? 4 : 0;
        float4 v = *reinterpret_cast<const float4*>(
            &w_hh[(size_t)(g * HH + jb * 16 + dloc) * HH + kq * 4]);
        *reinterpret_cast<float4*>(&ws[lrow * WS_STRIDE + kq * 4 + sw]) = v;
    }
    const float bh_r = (tid < 256) ? b_hh[e_dimg] : 0.f;
    const float bh_z = (tid < 256) ? b_hh[HH + e_dimg] : 0.f;
    const float bh_n = (tid < 256) ? b_hh[2 * HH + e_dimg] : 0.f;

    const ulonglong2* ws_v = reinterpret_cast<const ulonglong2*>(ws);
    int woff[6];
#pragma unroll
    for (int c = 0; c < 6; c++) {
        int g = c >> 1, dd = c & 1;
        int lrow = g * 16 + dg * 2 + dd;
        woff[c] = lrow * 129 + ((lrow >> 3) & 1) + ks;
    }
    __syncthreads();

    // h column base (floats) for this thread: 4*(ks + 16*kk)
    const int colb = 4 * ks;

    for (int t = 0; t < TT; t++) {
        const float* hprev = (t == 0) ? hxs : (out + (size_t)(t - 1) * NN * HH);

        // ---- prefetch step-constant epilogue operands (kernel-const data) ----
        float e_m = 0.f, e_ir = 0.f, e_iz = 0.f, e_inn = 0.f;
        int e_mm = 0, e_n = 0;
        if (tid < 256) {
            e_n = n0 + e_rloc;
            e_mm = t * NN + e_n;
            e_m = __ldg(&masks[e_mm]);
            const float* gi = g_gi + (size_t)e_mm * G3;
            e_ir  = __ldg(&gi[e_dimg]);
            e_iz  = __ldg(&gi[HH + e_dimg]);
            e_inn = __ldg(&gi[2 * HH + e_dimg]);
        }

        // ---- barrier wait at step start (t >= 1) ----
        if (t > 0) {
            if (tid == 0) {
                const unsigned tgt = 32u * (unsigned)t;
                unsigned e;
                do {
                    asm volatile("ld.acquire.gpu.global.u32 %0, [%1];"
                                 : "=r"(e) : "l"(&g_cnt[rb].v) : "memory");
                } while (e < tgt);
            }
            __syncthreads();
        }

        // ---- epilogue hval (fresh h, plain LDG) ----
        float e_h = 0.f;
        if (tid < 256)
            e_h = hprev[(size_t)e_n * HH + e_dimg];

        // ---- dot: direct-LDG h, smem w, double-buffered h ----
        ull acc[24];
#pragma unroll
        for (int s = 0; s < 24; s++) acc[s] = 0ull;

        const float* hr0 = hprev + (size_t)(n0 + rg) * HH;       // rows rg+4i
        float4 ha[4], hb[4];
#pragma unroll
        for (int i = 0; i < 4; i++)
            ha[i] = *reinterpret_cast<const float4*>(&hr0[(size_t)(4 * i) * HH + colb]);

#pragma unroll
        for (int kk = 0; kk < 8; kk++) {
            float4* cur = (kk & 1) ? hb : ha;
            float4* nxt = (kk & 1) ? ha : hb;
            if (kk < 7) {
                const int cn = colb + 64 * (kk + 1);
#pragma unroll
                for (int i = 0; i < 4; i++)
                    nxt[i] = *reinterpret_cast<const float4*>(&hr0[(size_t)(4 * i) * HH + cn]);
            }
            const int ko = kk * 16;
            ulonglong2 w2[6];
#pragma unroll
            for (int c = 0; c < 6; c++) w2[c] = ws_v[woff[c] + ko];
#pragma unroll
            for (int i = 0; i < 4; i++) {
                ull a01 = pack2(cur[i].x, cur[i].y);
                ull a23 = pack2(cur[i].z, cur[i].w);
#pragma unroll
                for (int c = 0; c < 6; c++) {
                    acc[i * 6 + c] = fma2(a01, w2[c].x, acc[i * 6 + c]);
                    acc[i * 6 + c] = fma2(a23, w2[c].y, acc[i * 6 + c]);
                }
            }
        }

        // ---- write partials (float-collapsed) ----
#pragma unroll
        for (int s = 0; s < 24; s++)
            red[s * RS_STRIDE + ks * 33 + pos] = lo32(acc[s]) + hi32(acc[s]);
        __syncthreads();

        // ---- epilogue (threads 0..255): reduce 16 slices, gates, store ----
        if (tid < 256) {
            float pr = 0.f, pz = 0.f, pn = 0.f;
            const int sr = (e_i * 6 + 0 + e_dd) * RS_STRIDE + e_pcol;
            const int sz = (e_i * 6 + 2 + e_dd) * RS_STRIDE + e_pcol;
            const int sn = (e_i * 6 + 4 + e_dd) * RS_STRIDE + e_pcol;
#pragma unroll
            for (int k = 0; k < 16; k++) {
                pr += red[sr + k * 33];
                pz += red[sz + k * 33];
                pn += red[sn + k * 33];
            }
            float ghr = pr * e_m + bh_r;
            float ghz = pz * e_m + bh_z;
            float ghn = pn * e_m + bh_n;

            float r = 1.0f / (1.0f + expf(-(e_ir + ghr)));
            float z = 1.0f / (1.0f + expf(-(e_iz + ghz)));
            float nc = tanhf(e_inn + r * ghn);
            float hval = e_m * e_h;
            float hnew = (1.0f - z) * nc + z * hval;

            out[(size_t)e_mm * HH + e_dimg] = hnew;
            if (t == TT - 1)
                out[(size_t)TT * NN * HH + (size_t)e_n * HH + e_dimg] = hnew;
        }
        __syncthreads();

        // ---- arrival (after epilogue visible CTA-wide) ----
        if (t < TT - 1 && tid == 0) {
            unsigned one = 1u;
            asm volatile("red.release.gpu.global.add.u32 [%0], %1;"
                         :: "l"(&g_cnt[rb].v), "r"(one) : "memory");
        }
    }
}

// =====================================================================
extern "C" void kernel_launch(void* const* d_in, const int* in_sizes, int n_in,
                              void* d_out, int out_size)
{
    const float* x      = (const float*)d_in[0];
    const float* hxs    = (const float*)d_in[1];
    const float* hxs_1  = (const float*)d_in[2];
    const float* masks  = (const float*)d_in[3];
    const float* w_ih   = (const float*)d_in[4];
    const float* w_hh   = (const float*)d_in[5];
    const float* b_ih   = (const float*)d_in[6];
    const float* b_hh   = (const float*)d_in[7];
    float* out = (float*)d_out;

    // third output: hxs_1 passthrough
    cudaMemcpyAsync(out + (size_t)(TT * NN + NN) * HH, hxs_1,
                    (size_t)NN * HH * sizeof(float), cudaMemcpyDeviceToDevice);

    // input projections (also resets barrier counters)
    dim3 g1(G3 / 64, (TT * NN) / 128);   // (24, 64)
    gemm_gi_kernel<<<g1, 256>>>(x, w_ih, b_ih);

    // persistent scan
    size_t shmem = (size_t)(48 * WS_STRIDE + 4 + 24 * RS_STRIDE) * sizeof(float); // 150,016 B
    cudaFuncSetAttribute(gru_scan_kernel,
                         cudaFuncAttributeMaxDynamicSharedMemorySize, (int)shmem);
    gru_scan_kernel<<<128, 512, shmem>>>(hxs, masks, w_hh, b_hh, out);
}

// round 8
// speedup vs baseline: 1.1190x; 1.1190x over previous
#include <cuda_runtime.h>
#include <cstdint>
#include <math.h>

// Problem dims
#define TT 128
#define NN 64
#define DD 512
#define HH 512
#define G3 1536   // 3*H

typedef unsigned long long ull;

// ---------------- packed f32x2 helpers ----------------
__device__ __forceinline__ ull fma2(ull a, ull b, ull c) {
    ull d;
    asm("fma.rn.f32x2 %0, %1, %2, %3;" : "=l"(d) : "l"(a), "l"(b), "l"(c));
    return d;
}
__device__ __forceinline__ float lo32(ull v) { return __uint_as_float((unsigned)(v & 0xffffffffu)); }
__device__ __forceinline__ float hi32(ull v) { return __uint_as_float((unsigned)(v >> 32)); }
__device__ __forceinline__ ull pack2(float x, float y) {
    return (((ull)__float_as_uint(y)) << 32) | (ull)__float_as_uint(x);
}

__device__ __forceinline__ float fsigmoid(float x) {
    return 1.0f / (1.0f + __expf(-x));
}
__device__ __forceinline__ float ftanh_fast(float x) {
    float ax = fabsf(x);
    float e = __expf(-2.0f * ax);
    float t = (1.0f - e) / (1.0f + e);
    return copysignf(t, x);
}

// ---------------- global scratch ----------------
// gi stored [m][g]: g_gi[m * 1536 + g]
__device__ float g_gi[(size_t)TT * NN * G3];

struct __align__(128) PadU { unsigned v; unsigned pad[31]; };
__device__ PadU g_cnt[8];   // [0..3]: A counters per row-group, [4..7]: B counters

// =====================================================================
// Kernel 1: gi[m, g] = sum_k x[m,k] * w_ih[g,k] + b_ih[g]
// Tiles 128(m) x 64(g), BK=32, 256 threads, 8x4 f2 thread tile,
// register double-buffered global->smem pipeline.
// =====================================================================
__global__ void __launch_bounds__(256, 2) gemm_gi_kernel(
    const float* __restrict__ x,
    const float* __restrict__ w_ih,
    const float* __restrict__ b_ih)
{
    if (blockIdx.x == 0 && blockIdx.y == 0 && threadIdx.x < 8)
        g_cnt[threadIdx.x].v = 0;

    __shared__ ull Ms[128 * 17];   // x rows (m)
    __shared__ ull Gs[64 * 17];    // w_ih rows (g)

    const int tid = threadIdx.x;
    const int g0 = blockIdx.x * 64;
    const int m0 = blockIdx.y * 128;
    const int tx = tid & 15;      // -> g group
    const int ty = tid >> 4;      // -> m group

    int mrow[4], mkq[4], grow[2], gkq[2];
#pragma unroll
    for (int i = 0; i < 4; i++) {
        int s = tid + i * 256;
        mrow[i] = s >> 3; mkq[i] = s & 7;
    }
#pragma unroll
    for (int i = 0; i < 2; i++) {
        int s = tid + i * 256;
        grow[i] = s >> 3; gkq[i] = s & 7;
    }

    ull acc[8][4];
#pragma unroll
    for (int i = 0; i < 8; i++)
#pragma unroll
        for (int j = 0; j < 4; j++) acc[i][j] = 0ull;

    float4 xm[4], xg[2];
#pragma unroll
    for (int i = 0; i < 4; i++)
        xm[i] = *reinterpret_cast<const float4*>(&x[(size_t)(m0 + mrow[i]) * DD + mkq[i] * 4]);
#pragma unroll
    for (int i = 0; i < 2; i++)
        xg[i] = *reinterpret_cast<const float4*>(&w_ih[(size_t)(g0 + grow[i]) * DD + gkq[i] * 4]);

    for (int k0 = 0; k0 < DD; k0 += 32) {
#pragma unroll
        for (int i = 0; i < 4; i++) {
            Ms[mrow[i] * 17 + mkq[i] * 2]     = pack2(xm[i].x, xm[i].y);
            Ms[mrow[i] * 17 + mkq[i] * 2 + 1] = pack2(xm[i].z, xm[i].w);
        }
#pragma unroll
        for (int i = 0; i < 2; i++) {
            Gs[grow[i] * 17 + gkq[i] * 2]     = pack2(xg[i].x, xg[i].y);
            Gs[grow[i] * 17 + gkq[i] * 2 + 1] = pack2(xg[i].z, xg[i].w);
        }
        __syncthreads();

        if (k0 + 32 < DD) {
            int kn = k0 + 32;
#pragma unroll
            for (int i = 0; i < 4; i++)
                xm[i] = *reinterpret_cast<const float4*>(&x[(size_t)(m0 + mrow[i]) * DD + kn + mkq[i] * 4]);
#pragma unroll
            for (int i = 0; i < 2; i++)
                xg[i] = *reinterpret_cast<const float4*>(&w_ih[(size_t)(g0 + grow[i]) * DD + kn + gkq[i] * 4]);
        }

#pragma unroll
        for (int kk = 0; kk < 16; kk++) {
            ull a[8], b[4];
#pragma unroll
            for (int i = 0; i < 8; i++) a[i] = Ms[(ty + 16 * i) * 17 + kk];
#pragma unroll
            for (int j = 0; j < 4; j++) b[j] = Gs[(tx + 16 * j) * 17 + kk];
#pragma unroll
            for (int i = 0; i < 8; i++)
#pragma unroll
                for (int j = 0; j < 4; j++)
                    acc[i][j] = fma2(a[i], b[j], acc[i][j]);
        }
        __syncthreads();
    }

    float bias[4];
#pragma unroll
    for (int j = 0; j < 4; j++) bias[j] = b_ih[g0 + tx + 16 * j];
#pragma unroll
    for (int i = 0; i < 8; i++) {
        int m = m0 + ty + 16 * i;
#pragma unroll
        for (int j = 0; j < 4; j++) {
            int g = g0 + tx + 16 * j;
            g_gi[(size_t)m * G3 + g] = lo32(acc[i][j]) + hi32(acc[i][j]) + bias[j];
        }
    }
}

// =====================================================================
// Kernel 2: persistent GRU scan, 128 CTAs x 544 threads.
// 4 row-groups (rb, 16 rows) x 32 dim-CTAs (jb, 16 dims).
// Warps 0..15 (512 threads) compute: round-6 data path
//   (smem h staging, LDS.128 dot, smem partial reduce), rows split
//   A = 0..7 / B = 8..15 with separate global counters.
// Warp 16 = sync warp: releases counters after named-barrier handshakes
//   with epilogue warps, polls next-step counters concurrently with
//   compute, publishes readiness via smem flags (cta release/acquire).
// =====================================================================
#define HS_STRIDE 516   // floats (129 ulonglong2)
#define WS_STRIDE 516
#define RS_STRIDE 530
#define NTHREADS 544

__global__ void __launch_bounds__(NTHREADS, 1) gru_scan_kernel(
    const float* __restrict__ hxs,
    const float* __restrict__ masks,
    const float* __restrict__ w_hh,
    const float* __restrict__ b_hh,
    float* __restrict__ out)
{
    extern __shared__ float smem[];
    float* hs  = smem;                                   // [16][516]
    float* ws  = smem + 16 * HS_STRIDE;                  // [48][516]
    float* red = smem + 16 * HS_STRIDE + 48 * WS_STRIDE; // [24][530]
    __shared__ unsigned sflag[2];                        // [0]=A ready step, [1]=B

    const int tid = threadIdx.x;
    const int wid = tid >> 5;
    const int lane = tid & 31;
    const int jb = blockIdx.x & 31;       // 16 dims: jb*16 ..
    const int rb = blockIdx.x >> 5;       // 16 rows: rb*16 ..
    const int n0 = rb * 16;

    uint32_t fA, fB;
    asm("{ .reg .u64 t; cvta.to.shared.u64 t, %1; cvt.u32.u64 %0, t; }"
        : "=r"(fA) : "l"(&sflag[0]));
    asm("{ .reg .u64 t; cvta.to.shared.u64 t, %1; cvt.u32.u64 %0, t; }"
        : "=r"(fB) : "l"(&sflag[1]));
    if (tid == 0) { sflag[0] = 0; sflag[1] = 0; }

    // ---- stage w_hh slice once: 48 rows (g*16+dloc) x 512 (all 544 help) ----
    for (int s = tid; s < 48 * 128; s += NTHREADS) {
        int lrow = s >> 7;            // 0..47
        int kq = s & 127;
        int g = lrow >> 4;
        int dloc = lrow & 15;
        float4 v = *reinterpret_cast<const float4*>(
            &w_hh[(size_t)(g * HH + jb * 16 + dloc) * HH + kq * 4]);
        *reinterpret_cast<float4*>(&ws[lrow * WS_STRIDE + kq * 4]) = v;
    }
    __syncthreads();

    // =================== SYNC WARP ===================
    if (wid == 16) {
        for (int t = 0; t < TT - 1; t++) {
            // A handshake: wait for warps 0..3 epilogue stores, release cntA
            asm volatile("bar.sync 3, 160;" ::: "memory");
            if (lane == 0)
                asm volatile("red.release.gpu.global.add.u32 [%0], %1;"
                             :: "l"(&g_cnt[rb].v), "r"(1u) : "memory");
            // B handshake
            asm volatile("bar.sync 4, 160;" ::: "memory");
            if (lane == 0)
                asm volatile("red.release.gpu.global.add.u32 [%0], %1;"
                             :: "l"(&g_cnt[4 + rb].v), "r"(1u) : "memory");

            // poll next-step counters (converged warp, all lanes same addr)
            const unsigned tgt = 32u * (unsigned)(t + 1);
            unsigned e;
            do {
                asm volatile("ld.acquire.gpu.global.u32 %0, [%1];"
                             : "=r"(e) : "l"(&g_cnt[rb].v) : "memory");
            } while (e < tgt);
            asm volatile("st.release.cta.shared.u32 [%0], %1;"
                         :: "r"(fA), "r"((unsigned)(t + 1)) : "memory");
            do {
                asm volatile("ld.acquire.gpu.global.u32 %0, [%1];"
                             : "=r"(e) : "l"(&g_cnt[4 + rb].v) : "memory");
            } while (e < tgt);
            asm volatile("st.release.cta.shared.u32 [%0], %1;"
                         :: "r"(fB), "r"((unsigned)(t + 1)) : "memory");
        }
        return;
    }

    // =================== COMPUTE WARPS (512 threads) ===================
    const int ks = tid >> 5;              // 0..15 (K slice)
    const int pos = tid & 31;
    const int rg = pos & 3;               // row in group of 4
    const int dg = pos >> 2;              // 0..7 dim pair

    // epilogue mapping (threads 0..255): 1 output each (16 rows x 16 dims)
    const int e_dim  = tid & 15;
    const int e_rloc = tid >> 4;              // valid for tid < 256
    const int e_dimg = jb * 16 + e_dim;
    const int e_i  = (e_rloc >> 2) & 3;
    const int e_rg = e_rloc & 3;
    const int e_dg = e_dim >> 1;
    const int e_dd = e_dim & 1;
    const int e_pcol = e_dg * 4 + e_rg;

    const float bh_r = (tid < 256) ? b_hh[e_dimg] : 0.f;
    const float bh_z = (tid < 256) ? b_hh[HH + e_dimg] : 0.f;
    const float bh_n = (tid < 256) ? b_hh[2 * HH + e_dimg] : 0.f;

    const ulonglong2* ws_v = reinterpret_cast<const ulonglong2*>(ws);
    const ulonglong2* hs_v = reinterpret_cast<const ulonglong2*>(hs);
    const ulonglong2* hp = hs_v + rg * 129 + ks;
    int woff[6];
#pragma unroll
    for (int c = 0; c < 6; c++) {
        int g = c >> 1, dd = c & 1;
        woff[c] = (g * 16 + dg * 2 + dd) * 129 + ks;
    }

    for (int t = 0; t < TT; t++) {
        const float* hprev = (t == 0) ? hxs : (out + (size_t)(t - 1) * NN * HH);

        // ---- prefetch epilogue operands independent of h ----
        float e_m = 0.f, e_ir = 0.f, e_iz = 0.f, e_inn = 0.f;
        int e_mm = 0, e_n = 0;
        if (tid < 256) {
            e_n = n0 + e_rloc;
            e_mm = t * NN + e_n;
            e_m = __ldg(&masks[e_mm]);
            const float* gi = g_gi + (size_t)e_mm * G3;
            e_ir  = __ldg(&gi[e_dimg]);
            e_iz  = __ldg(&gi[HH + e_dimg]);
            e_inn = __ldg(&gi[2 * HH + e_dimg]);
        }

        // ---- wait A ready, stage A rows (0..7) ----
        if (t > 0) {
            unsigned f;
            do {
                asm volatile("ld.acquire.cta.shared.u32 %0, [%1];"
                             : "=r"(f) : "r"(fA) : "memory");
            } while (f < (unsigned)t);
        }
#pragma unroll
        for (int i = 0; i < 2; i++) {
            int s = tid + i * 512;        // 8 rows x 128 float4
            int row = s >> 7;
            int kq = s & 127;
            float4 v = __ldcg(reinterpret_cast<const float4*>(
                &hprev[(size_t)(n0 + row) * HH + kq * 4]));
            *reinterpret_cast<float4*>(&hs[row * HS_STRIDE + kq * 4]) = v;
        }
        asm volatile("bar.sync 1, 512;" ::: "memory");

        ull acc[24];
#pragma unroll
        for (int s = 0; s < 24; s++) acc[s] = 0ull;

        // ---- dot A (rows rg, rg+4 -> acc i=0,1) ----
#pragma unroll 2
        for (int kk = 0; kk < 8; kk++) {
            const int ko = kk * 16;
            ulonglong2 a2[2];
            a2[0] = hp[ko];
            a2[1] = hp[4 * 129 + ko];
            ulonglong2 w2[6];
#pragma unroll
            for (int c = 0; c < 6; c++) w2[c] = ws_v[woff[c] + ko];
#pragma unroll
            for (int i = 0; i < 2; i++)
#pragma unroll
                for (int c = 0; c < 6; c++) {
                    acc[i * 6 + c] = fma2(a2[i].x, w2[c].x, acc[i * 6 + c]);
                    acc[i * 6 + c] = fma2(a2[i].y, w2[c].y, acc[i * 6 + c]);
                }
        }

        // ---- wait B ready (usually instant), stage B rows (8..15) ----
        if (t > 0) {
            unsigned f;
            do {
                asm volatile("ld.acquire.cta.shared.u32 %0, [%1];"
                             : "=r"(f) : "r"(fB) : "memory");
            } while (f < (unsigned)t);
        }
#pragma unroll
        for (int i = 0; i < 2; i++) {
            int s = tid + i * 512;
            int row = 8 + (s >> 7);
            int kq = s & 127;
            float4 v = __ldcg(reinterpret_cast<const float4*>(
                &hprev[(size_t)(n0 + row) * HH + kq * 4]));
            *reinterpret_cast<float4*>(&hs[row * HS_STRIDE + kq * 4]) = v;
        }
        asm volatile("bar.sync 1, 512;" ::: "memory");

        // epilogue hval from global (own-write, L1-coherent)
        float e_h = 0.f;
        if (tid < 256)
            e_h = hprev[(size_t)e_n * HH + e_dimg];

        // ---- dot B (rows rg+8, rg+12 -> acc i=2,3) ----
#pragma unroll 2
        for (int kk = 0; kk < 8; kk++) {
            const int ko = kk * 16;
            ulonglong2 a2[2];
            a2[0] = hp[8 * 129 + ko];
            a2[1] = hp[12 * 129 + ko];
            ulonglong2 w2[6];
#pragma unroll
            for (int c = 0; c < 6; c++) w2[c] = ws_v[woff[c] + ko];
#pragma unroll
            for (int i = 0; i < 2; i++)
#pragma unroll
                for (int c = 0; c < 6; c++) {
                    acc[(i + 2) * 6 + c] = fma2(a2[i].x, w2[c].x, acc[(i + 2) * 6 + c]);
                    acc[(i + 2) * 6 + c] = fma2(a2[i].y, w2[c].y, acc[(i + 2) * 6 + c]);
                }
        }

        // ---- write partials (float-collapsed) ----
#pragma unroll
        for (int s = 0; s < 24; s++)
            red[s * RS_STRIDE + ks * 33 + pos] = lo32(acc[s]) + hi32(acc[s]);
        asm volatile("bar.sync 1, 512;" ::: "memory");

        // ---- epilogue (threads 0..255): reduce 16 slices, gates, store ----
        if (tid < 256) {
            float pr = 0.f, pz = 0.f, pn = 0.f;
            const int sr = (e_i * 6 + 0 + e_dd) * RS_STRIDE + e_pcol;
            const int sz = (e_i * 6 + 2 + e_dd) * RS_STRIDE + e_pcol;
            const int sn = (e_i * 6 + 4 + e_dd) * RS_STRIDE + e_pcol;
#pragma unroll
            for (int k = 0; k < 16; k++) {
                pr += red[sr + k * 33];
                pz += red[sz + k * 33];
                pn += red[sn + k * 33];
            }
            float ghr = pr * e_m + bh_r;
            float ghz = pz * e_m + bh_z;
            float ghn = pn * e_m + bh_n;

            float r = fsigmoid(e_ir + ghr);
            float z = fsigmoid(e_iz + ghz);
            float nc = ftanh_fast(e_inn + r * ghn);
            float hval = e_m * e_h;
            float hnew = (1.0f - z) * nc + z * hval;

            out[(size_t)e_mm * HH + e_dimg] = hnew;
            if (t == TT - 1)
                out[(size_t)TT * NN * HH + (size_t)e_n * HH + e_dimg] = hnew;
        }

        // ---- arrivals: A warps then B warps handshake with sync warp ----
        if (t < TT - 1) {
            if (wid < 4)
                asm volatile("bar.arrive 3, 160;" ::: "memory");
            else if (wid < 8)
                asm volatile("bar.arrive 4, 160;" ::: "memory");
        }
    }
}

// =====================================================================
extern "C" void kernel_launch(void* const* d_in, const int* in_sizes, int n_in,
                              void* d_out, int out_size)
{
    const float* x      = (const float*)d_in[0];
    const float* hxs    = (const float*)d_in[1];
    const float* hxs_1  = (const float*)d_in[2];
    const float* masks  = (const float*)d_in[3];
    const float* w_ih   = (const float*)d_in[4];
    const float* w_hh   = (const float*)d_in[5];
    const float* b_ih   = (const float*)d_in[6];
    const float* b_hh   = (const float*)d_in[7];
    float* out = (float*)d_out;

    // third output: hxs_1 passthrough
    cudaMemcpyAsync(out + (size_t)(TT * NN + NN) * HH, hxs_1,
                    (size_t)NN * HH * sizeof(float), cudaMemcpyDeviceToDevice);

    // input projections (also resets barrier counters)
    dim3 g1(G3 / 64, (TT * NN) / 128);   // (24, 64)
    gemm_gi_kernel<<<g1, 256>>>(x, w_ih, b_ih);

    // persistent scan
    size_t shmem = (size_t)(16 * HS_STRIDE + 48 * WS_STRIDE + 24 * RS_STRIDE)
                   * sizeof(float);   // 182,976 B
    cudaFuncSetAttribute(gru_scan_kernel,
                         cudaFuncAttributeMaxDynamicSharedMemorySize, (int)shmem);
    gru_scan_kernel<<<128, NTHREADS, shmem>>>(hxs, masks, w_hh, b_hh, out);
}

// round 9
// speedup vs baseline: 1.3194x; 1.1791x over previous
#include <cuda_runtime.h>
#include <cstdint>
#include <math.h>

// Problem dims
#define TT 128
#define NN 64
#define DD 512
#define HH 512
#define G3 1536   // 3*H

typedef unsigned long long ull;

// ---------------- packed f32x2 helpers ----------------
__device__ __forceinline__ ull fma2(ull a, ull b, ull c) {
    ull d;
    asm("fma.rn.f32x2 %0, %1, %2, %3;" : "=l"(d) : "l"(a), "l"(b), "l"(c));
    return d;
}
__device__ __forceinline__ float lo32(ull v) { return __uint_as_float((unsigned)(v & 0xffffffffu)); }
__device__ __forceinline__ float hi32(ull v) { return __uint_as_float((unsigned)(v >> 32)); }
__device__ __forceinline__ ull pack2(float x, float y) {
    return (((ull)__float_as_uint(y)) << 32) | (ull)__float_as_uint(x);
}

__device__ __forceinline__ float fsigmoid(float x) {
    return 1.0f / (1.0f + __expf(-x));
}
__device__ __forceinline__ float ftanh_fast(float x) {
    float ax = fabsf(x);
    float e = __expf(-2.0f * ax);
    float t = (1.0f - e) / (1.0f + e);
    return copysignf(t, x);
}

// ---------------- global scratch ----------------
// gi stored [m][g]: g_gi[m * 1536 + g]
__device__ float g_gi[(size_t)TT * NN * G3];

struct __align__(128) PadU { unsigned v; unsigned pad[31]; };
__device__ PadU g_cnt[4];   // accumulating counter per row-group

// =====================================================================
// Kernel 1: gi[m, g] = sum_k x[m,k] * w_ih[g,k] + b_ih[g]
// Tiles 128(m) x 64(g), BK=32, 256 threads, 8x4 f2 thread tile,
// register double-buffered global->smem pipeline.
// =====================================================================
__global__ void __launch_bounds__(256, 2) gemm_gi_kernel(
    const float* __restrict__ x,
    const float* __restrict__ w_ih,
    const float* __restrict__ b_ih)
{
    if (blockIdx.x == 0 && blockIdx.y == 0 && threadIdx.x < 4)
        g_cnt[threadIdx.x].v = 0;

    __shared__ ull Ms[128 * 17];   // x rows (m)
    __shared__ ull Gs[64 * 17];    // w_ih rows (g)

    const int tid = threadIdx.x;
    const int g0 = blockIdx.x * 64;
    const int m0 = blockIdx.y * 128;
    const int tx = tid & 15;      // -> g group
    const int ty = tid >> 4;      // -> m group

    int mrow[4], mkq[4], grow[2], gkq[2];
#pragma unroll
    for (int i = 0; i < 4; i++) {
        int s = tid + i * 256;
        mrow[i] = s >> 3; mkq[i] = s & 7;
    }
#pragma unroll
    for (int i = 0; i < 2; i++) {
        int s = tid + i * 256;
        grow[i] = s >> 3; gkq[i] = s & 7;
    }

    ull acc[8][4];
#pragma unroll
    for (int i = 0; i < 8; i++)
#pragma unroll
        for (int j = 0; j < 4; j++) acc[i][j] = 0ull;

    float4 xm[4], xg[2];
#pragma unroll
    for (int i = 0; i < 4; i++)
        xm[i] = *reinterpret_cast<const float4*>(&x[(size_t)(m0 + mrow[i]) * DD + mkq[i] * 4]);
#pragma unroll
    for (int i = 0; i < 2; i++)
        xg[i] = *reinterpret_cast<const float4*>(&w_ih[(size_t)(g0 + grow[i]) * DD + gkq[i] * 4]);

    for (int k0 = 0; k0 < DD; k0 += 32) {
#pragma unroll
        for (int i = 0; i < 4; i++) {
            Ms[mrow[i] * 17 + mkq[i] * 2]     = pack2(xm[i].x, xm[i].y);
            Ms[mrow[i] * 17 + mkq[i] * 2 + 1] = pack2(xm[i].z, xm[i].w);
        }
#pragma unroll
        for (int i = 0; i < 2; i++) {
            Gs[grow[i] * 17 + gkq[i] * 2]     = pack2(xg[i].x, xg[i].y);
            Gs[grow[i] * 17 + gkq[i] * 2 + 1] = pack2(xg[i].z, xg[i].w);
        }
        __syncthreads();

        if (k0 + 32 < DD) {
            int kn = k0 + 32;
#pragma unroll
            for (int i = 0; i < 4; i++)
                xm[i] = *reinterpret_cast<const float4*>(&x[(size_t)(m0 + mrow[i]) * DD + kn + mkq[i] * 4]);
#pragma unroll
            for (int i = 0; i < 2; i++)
                xg[i] = *reinterpret_cast<const float4*>(&w_ih[(size_t)(g0 + grow[i]) * DD + kn + gkq[i] * 4]);
        }

#pragma unroll
        for (int kk = 0; kk < 16; kk++) {
            ull a[8], b[4];
#pragma unroll
            for (int i = 0; i < 8; i++) a[i] = Ms[(ty + 16 * i) * 17 + kk];
#pragma unroll
            for (int j = 0; j < 4; j++) b[j] = Gs[(tx + 16 * j) * 17 + kk];
#pragma unroll
            for (int i = 0; i < 8; i++)
#pragma unroll
                for (int j = 0; j < 4; j++)
                    acc[i][j] = fma2(a[i], b[j], acc[i][j]);
        }
        __syncthreads();
    }

    float bias[4];
#pragma unroll
    for (int j = 0; j < 4; j++) bias[j] = b_ih[g0 + tx + 16 * j];
#pragma unroll
    for (int i = 0; i < 8; i++) {
        int m = m0 + ty + 16 * i;
#pragma unroll
        for (int j = 0; j < 4; j++) {
            int g = g0 + tx + 16 * j;
            g_gi[(size_t)m * G3 + g] = lo32(acc[i][j]) + hi32(acc[i][j]) + bias[j];
        }
    }
}

// =====================================================================
// Kernel 2: persistent GRU scan, 128 CTAs x 512 threads.
// 4 row-groups (rb, 16 rows) x 32 dim-CTAs (jb, 16 dims).
// Dot identical round-6 path: all 512 threads, smem h + swizzled smem w,
// LDS.128, 4 rows x 6 gate-cols x 16 k-slices, smem partial reduce.
// Serial-tail split: warps 0-7 = epilogue+release; warps 8-15 = poll+stage
// next h, concurrently. hval carried in register across steps.
// =====================================================================
#define HS_STRIDE 516   // floats (129 ulonglong2)
#define WS_STRIDE 516
#define RS_STRIDE 530

__global__ void __launch_bounds__(512, 1) gru_scan_kernel(
    const float* __restrict__ hxs,
    const float* __restrict__ masks,
    const float* __restrict__ w_hh,
    const float* __restrict__ b_hh,
    float* __restrict__ out)
{
    extern __shared__ float smem[];
    float* hs  = smem;                                   // [16][516]
    float* ws  = smem + 16 * HS_STRIDE;                  // [48][516] (swizzled)
    float* red = smem + 16 * HS_STRIDE + 48 * WS_STRIDE; // [24][530]

    const int tid = threadIdx.x;
    const int wid = tid >> 5;
    const int jb = blockIdx.x & 31;       // 16 dims: jb*16 ..
    const int rb = blockIdx.x >> 5;       // 16 rows: rb*16 ..
    const int n0 = rb * 16;
    const int ks = tid >> 5;              // 0..15 (K slice)
    const int pos = tid & 31;
    const int rg = pos & 3;               // row in group of 4
    const int dg = pos >> 2;              // 0..7 dim pair

    // epilogue mapping (threads 0..255 == warps 0..7): 1 output each
    const int e_dim  = tid & 15;
    const int e_rloc = tid >> 4;
    const int e_dimg = jb * 16 + e_dim;
    const int e_i  = (e_rloc >> 2) & 3;
    const int e_rg = e_rloc & 3;
    const int e_dg = e_dim >> 1;
    const int e_dd = e_dim & 1;
    const int e_pcol = e_dg * 4 + e_rg;

    // ---- stage w_hh slice once: 48 rows (g*16+dloc) x 512, bank-swizzled ----
#pragma unroll
    for (int i = 0; i < 12; i++) {
        int s = tid + i * 512;        // 48 rows x 128 float4
        int lrow = s >> 7;            // 0..47
        int kq = s & 127;
        int g = lrow >> 4;
        int dloc = lrow & 15;
        int sw = (lrow & 8) ? 4 : 0;
        float4 v = *reinterpret_cast<const float4*>(
            &w_hh[(size_t)(g * HH + jb * 16 + dloc) * HH + kq * 4]);
        *reinterpret_cast<float4*>(&ws[lrow * WS_STRIDE + kq * 4 + sw]) = v;
    }
    const float bh_r = (wid < 8) ? b_hh[e_dimg] : 0.f;
    const float bh_z = (wid < 8) ? b_hh[HH + e_dimg] : 0.f;
    const float bh_n = (wid < 8) ? b_hh[2 * HH + e_dimg] : 0.f;

    const ulonglong2* ws_v = reinterpret_cast<const ulonglong2*>(ws);
    const ulonglong2* hs_v = reinterpret_cast<const ulonglong2*>(hs);
    const ulonglong2* hp = hs_v + rg * 129 + ks;
    int woff[6];
#pragma unroll
    for (int c = 0; c < 6; c++) {
        int g = c >> 1, dd = c & 1;
        int lrow = g * 16 + dg * 2 + dd;
        woff[c] = lrow * 129 + ((lrow >> 3) & 1) + ks;
    }

    float hprev_reg = 0.f;   // epilogue threads: h[t-1] at (e_n, e_dimg)

    for (int t = 0; t < TT; t++) {
        // ======= serial-tail roles (converge at __syncthreads below) =======
        float e_m = 0.f, e_ir = 0.f, e_iz = 0.f, e_inn = 0.f;
        int e_mm = 0, e_n = 0;
        if (wid < 8) {
            // epilogue operand prefetch for step t (overlaps peer stage/poll)
            e_n = n0 + e_rloc;
            e_mm = t * NN + e_n;
            e_m = __ldg(&masks[e_mm]);
            const float* gi = g_gi + (size_t)e_mm * G3;
            e_ir  = __ldg(&gi[e_dimg]);
            e_iz  = __ldg(&gi[HH + e_dimg]);
            e_inn = __ldg(&gi[2 * HH + e_dimg]);
            if (t == 0)
                hprev_reg = hxs[(size_t)e_n * HH + e_dimg];
        } else {
            // wait for h(t) visibility, then stage 16 rows x 512 floats
            if (t > 0) {
                if (tid == 256) {
                    const unsigned tgt = 32u * (unsigned)t;
                    unsigned e;
                    do {
                        asm volatile("ld.acquire.gpu.global.u32 %0, [%1];"
                                     : "=r"(e) : "l"(&g_cnt[rb].v) : "memory");
                    } while (e < tgt);
                }
                asm volatile("bar.sync 3, 256;" ::: "memory");
            }
            const float* hsrc = (t == 0) ? hxs : (out + (size_t)(t - 1) * NN * HH);
            const int lt = tid - 256;
#pragma unroll
            for (int i = 0; i < 8; i++) {
                int s = lt + i * 256;         // 16 rows x 128 float4
                int row = s >> 7;
                int kq = s & 127;
                float4 v = __ldcg(reinterpret_cast<const float4*>(
                    &hsrc[(size_t)(n0 + row) * HH + kq * 4]));
                *reinterpret_cast<float4*>(&hs[row * HS_STRIDE + kq * 4]) = v;
            }
        }
        __syncthreads();

        // ======= register-tiled dot (all 512 threads, round-6 path) =======
        ull acc[24];
#pragma unroll
        for (int s = 0; s < 24; s++) acc[s] = 0ull;

#pragma unroll 2
        for (int kk = 0; kk < 8; kk++) {
            const int ko = kk * 16;
            ulonglong2 a2[4];
#pragma unroll
            for (int i = 0; i < 4; i++) a2[i] = hp[i * (4 * 129) + ko];
            ulonglong2 w2[6];
#pragma unroll
            for (int c = 0; c < 6; c++) w2[c] = ws_v[woff[c] + ko];
#pragma unroll
            for (int i = 0; i < 4; i++)
#pragma unroll
                for (int c = 0; c < 6; c++) {
                    acc[i * 6 + c] = fma2(a2[i].x, w2[c].x, acc[i * 6 + c]);
                    acc[i * 6 + c] = fma2(a2[i].y, w2[c].y, acc[i * 6 + c]);
                }
        }

        // ---- write partials (float-collapsed) ----
#pragma unroll
        for (int s = 0; s < 24; s++)
            red[s * RS_STRIDE + ks * 33 + pos] = lo32(acc[s]) + hi32(acc[s]);
        __syncthreads();

        // ======= epilogue tail: warps 0-7 only =======
        if (wid < 8) {
            float pr = 0.f, pz = 0.f, pn = 0.f;
            const int sr = (e_i * 6 + 0 + e_dd) * RS_STRIDE + e_pcol;
            const int sz = (e_i * 6 + 2 + e_dd) * RS_STRIDE + e_pcol;
            const int sn = (e_i * 6 + 4 + e_dd) * RS_STRIDE + e_pcol;
#pragma unroll
            for (int k = 0; k < 16; k++) {
                pr += red[sr + k * 33];
                pz += red[sz + k * 33];
                pn += red[sn + k * 33];
            }
            float ghr = pr * e_m + bh_r;
            float ghz = pz * e_m + bh_z;
            float ghn = pn * e_m + bh_n;

            float r = fsigmoid(e_ir + ghr);
            float z = fsigmoid(e_iz + ghz);
            float nc = ftanh_fast(e_inn + r * ghn);
            float hval = e_m * hprev_reg;
            float hnew = (1.0f - z) * nc + z * hval;
            hprev_reg = hnew;

            out[(size_t)e_mm * HH + e_dimg] = hnew;
            if (t == TT - 1)
                out[(size_t)TT * NN * HH + (size_t)e_n * HH + e_dimg] = hnew;

            asm volatile("bar.sync 2, 256;" ::: "memory");
            if (tid == 0 && t < TT - 1)
                asm volatile("red.release.gpu.global.add.u32 [%0], %1;"
                             :: "l"(&g_cnt[rb].v), "r"(1u) : "memory");
        }
        // warps 8-15 fall through to next iteration's poll+stage immediately
    }
}

// =====================================================================
extern "C" void kernel_launch(void* const* d_in, const int* in_sizes, int n_in,
                              void* d_out, int out_size)
{
    const float* x      = (const float*)d_in[0];
    const float* hxs    = (const float*)d_in[1];
    const float* hxs_1  = (const float*)d_in[2];
    const float* masks  = (const float*)d_in[3];
    const float* w_ih   = (const float*)d_in[4];
    const float* w_hh   = (const float*)d_in[5];
    const float* b_ih   = (const float*)d_in[6];
    const float* b_hh   = (const float*)d_in[7];
    float* out = (float*)d_out;

    // third output: hxs_1 passthrough
    cudaMemcpyAsync(out + (size_t)(TT * NN + NN) * HH, hxs_1,
                    (size_t)NN * HH * sizeof(float), cudaMemcpyDeviceToDevice);

    // input projections (also resets barrier counters)
    dim3 g1(G3 / 64, (TT * NN) / 128);   // (24, 64)
    gemm_gi_kernel<<<g1, 256>>>(x, w_ih, b_ih);

    // persistent scan
    size_t shmem = (size_t)(16 * HS_STRIDE + 48 * WS_STRIDE + 24 * RS_STRIDE)
                   * sizeof(float);   // 182,976 B
    cudaFuncSetAttribute(gru_scan_kernel,
                         cudaFuncAttributeMaxDynamicSharedMemorySize, (int)shmem);
    gru_scan_kernel<<<128, 512, shmem>>>(hxs, masks, w_hh, b_hh, out);
}

// round 11
// speedup vs baseline: 1.6078x; 1.2186x over previous
#include <cuda_runtime.h>
#include <cuda_bf16.h>
#include <cstdint>
#include <math.h>

// Problem dims
#define TT 128
#define NN 64
#define DD 512
#define HH 512
#define G3 1536   // 3*H

typedef unsigned long long ull;

// ---------------- packed f32x2 helpers (scan) ----------------
__device__ __forceinline__ ull fma2(ull a, ull b, ull c) {
    ull d;
    asm("fma.rn.f32x2 %0, %1, %2, %3;" : "=l"(d) : "l"(a), "l"(b), "l"(c));
    return d;
}
__device__ __forceinline__ float lo32(ull v) { return __uint_as_float((unsigned)(v & 0xffffffffu)); }
__device__ __forceinline__ float hi32(ull v) { return __uint_as_float((unsigned)(v >> 32)); }

__device__ __forceinline__ float fsigmoid(float x) {
    return 1.0f / (1.0f + __expf(-x));
}
__device__ __forceinline__ float ftanh_fast(float x) {
    float ax = fabsf(x);
    float e = __expf(-2.0f * ax);
    float t = (1.0f - e) / (1.0f + e);
    return copysignf(t, x);
}

// ---------------- mma helpers (baseline PTX, no 'a' features) ----------------
__device__ __forceinline__ uint32_t smem_u32(const void* p) {
    uint32_t a;
    asm("{ .reg .u64 t; cvta.to.shared.u64 t, %1; cvt.u32.u64 %0, t; }" : "=r"(a) : "l"(p));
    return a;
}
__device__ __forceinline__ void ldsm_x4(uint32_t& r0, uint32_t& r1, uint32_t& r2,
                                        uint32_t& r3, uint32_t addr) {
    asm volatile("ldmatrix.sync.aligned.m8n8.x4.shared.b16 {%0,%1,%2,%3}, [%4];"
                 : "=r"(r0), "=r"(r1), "=r"(r2), "=r"(r3) : "r"(addr));
}
__device__ __forceinline__ void mma_bf16(float* d, const uint32_t* a,
                                         uint32_t b0, uint32_t b1) {
    asm volatile("mma.sync.aligned.m16n8k16.row.col.f32.bf16.bf16.f32 "
                 "{%0,%1,%2,%3}, {%4,%5,%6,%7}, {%8,%9}, {%0,%1,%2,%3};"
                 : "+f"(d[0]), "+f"(d[1]), "+f"(d[2]), "+f"(d[3])
                 : "r"(a[0]), "r"(a[1]), "r"(a[2]), "r"(a[3]), "r"(b0), "r"(b1));
}
// split two fp32 into packed bf16 hi pair and lo pair
__device__ __forceinline__ void split2(float a, float b, unsigned& hi, unsigned& lo) {
    __nv_bfloat16 ha = __float2bfloat16(a), hb = __float2bfloat16(b);
    hi = ((unsigned)__bfloat16_as_ushort(hb) << 16) | __bfloat16_as_ushort(ha);
    __nv_bfloat16 la = __float2bfloat16(a - __bfloat162float(ha));
    __nv_bfloat16 lb = __float2bfloat16(b - __bfloat162float(hb));
    lo = ((unsigned)__bfloat16_as_ushort(lb) << 16) | __bfloat16_as_ushort(la);
}

// ---------------- global scratch ----------------
__device__ float g_gi[(size_t)TT * NN * G3];   // gi[m][g]

struct __align__(128) PadU { unsigned v; unsigned pad[31]; };
__device__ PadU g_cnt[4];   // accumulating counter per scan row-group

// =====================================================================
// Kernel 1: tensor-core bf16-split GEMM via mma.sync (HMMA path).
// gi[m,g] = x[m]·w_ih[g] + b_ih[g] ≈ xhi·whi + xhi·wlo + xlo·whi.
// CTA 128(m) x 64(g), BK=64, 256 threads = 4x2 warps of 32x32 tiles.
// fp32->bf16 hi/lo split fused into staging. Smem stride 72 bf16.
// =====================================================================
#define BK 64
#define A_STR 72                       // bf16 elems per row
#define AHI_B 0
#define ALO_B 18432                    // 128*72*2
#define BHI_B 36864
#define BLO_B 46080                    // +64*72*2
#define BIAS_B 55296
#define GM_SMEM (55296 + 256)

__global__ void __launch_bounds__(256, 2) gemm_mma_kernel(
    const float* __restrict__ x,
    const float* __restrict__ w_ih,
    const float* __restrict__ b_ih)
{
    if (blockIdx.x == 0 && blockIdx.y == 0 && threadIdx.x < 4)
        g_cnt[threadIdx.x].v = 0;

    extern __shared__ char sm[];
    const uint32_t sb = smem_u32(sm);
    float* bias = reinterpret_cast<float*>(sm + BIAS_B);

    const int tid = threadIdx.x;
    const int wid = tid >> 5;
    const int l = tid & 31;
    const int g0 = blockIdx.x * 64;
    const int m0 = blockIdx.y * 128;
    const int m_base = (wid & 3) * 32;
    const int n_base = (wid >> 2) * 32;

    if (tid < 64) bias[tid] = b_ih[g0 + tid];

    // ldmatrix byte offsets (per thread, + kk*32 per k16 step)
    uint32_t aoff[2], boff[2];
#pragma unroll
    for (int mt = 0; mt < 2; mt++)
        aoff[mt] = ((m_base + mt * 16 + (l & 15)) * A_STR + (l >> 4) * 8) * 2;
#pragma unroll
    for (int p = 0; p < 2; p++)
        boff[p] = ((n_base + p * 16 + (l & 7) + ((l >> 4) & 1) * 8) * A_STR
                   + ((l >> 3) & 1) * 8) * 2;

    float d[2][4][4];
#pragma unroll
    for (int mt = 0; mt < 2; mt++)
#pragma unroll
        for (int nt = 0; nt < 4; nt++)
#pragma unroll
            for (int r = 0; r < 4; r++) d[mt][nt][r] = 0.f;

    for (int kc = 0; kc < DD; kc += BK) {
        // ---- stage A (x): 128 rows x 64 cols, split hi/lo ----
#pragma unroll
        for (int it = 0; it < 8; it++) {
            int s = tid + it * 256;
            int row = s >> 4, cq = s & 15;
            float4 v = *reinterpret_cast<const float4*>(
                &x[(size_t)(m0 + row) * DD + kc + cq * 4]);
            unsigned h01, l01, h23, l23;
            split2(v.x, v.y, h01, l01);
            split2(v.z, v.w, h23, l23);
            int eo = (row * A_STR + cq * 4) * 2;
            *reinterpret_cast<uint2*>(sm + AHI_B + eo) = make_uint2(h01, h23);
            *reinterpret_cast<uint2*>(sm + ALO_B + eo) = make_uint2(l01, l23);
        }
        // ---- stage B (w_ih): 64 rows x 64 cols ----
#pragma unroll
        for (int it = 0; it < 4; it++) {
            int s = tid + it * 256;
            int row = s >> 4, cq = s & 15;
            float4 v = *reinterpret_cast<const float4*>(
                &w_ih[(size_t)(g0 + row) * DD + kc + cq * 4]);
            unsigned h01, l01, h23, l23;
            split2(v.x, v.y, h01, l01);
            split2(v.z, v.w, h23, l23);
            int eo = (row * A_STR + cq * 4) * 2;
            *reinterpret_cast<uint2*>(sm + BHI_B + eo) = make_uint2(h01, h23);
            *reinterpret_cast<uint2*>(sm + BLO_B + eo) = make_uint2(l01, l23);
        }
        __syncthreads();

#pragma unroll
        for (int kk = 0; kk < BK / 16; kk++) {
            const uint32_t ko = kk * 32;   // bytes
            uint32_t ahi[2][4], alo[2][4], bhi[2][4], blo[2][4];
#pragma unroll
            for (int mt = 0; mt < 2; mt++) {
                ldsm_x4(ahi[mt][0], ahi[mt][1], ahi[mt][2], ahi[mt][3],
                        sb + AHI_B + aoff[mt] + ko);
                ldsm_x4(alo[mt][0], alo[mt][1], alo[mt][2], alo[mt][3],
                        sb + ALO_B + aoff[mt] + ko);
            }
#pragma unroll
            for (int p = 0; p < 2; p++) {
                ldsm_x4(bhi[p][0], bhi[p][1], bhi[p][2], bhi[p][3],
                        sb + BHI_B + boff[p] + ko);
                ldsm_x4(blo[p][0], blo[p][1], blo[p][2], blo[p][3],
                        sb + BLO_B + boff[p] + ko);
            }
#pragma unroll
            for (int mt = 0; mt < 2; mt++)
#pragma unroll
                for (int p = 0; p < 2; p++)
#pragma unroll
                    for (int sub = 0; sub < 2; sub++) {
                        int nt = p * 2 + sub;
                        mma_bf16(d[mt][nt], ahi[mt], bhi[p][sub * 2], bhi[p][sub * 2 + 1]);
                        mma_bf16(d[mt][nt], ahi[mt], blo[p][sub * 2], blo[p][sub * 2 + 1]);
                        mma_bf16(d[mt][nt], alo[mt], bhi[p][sub * 2], bhi[p][sub * 2 + 1]);
                    }
        }
        __syncthreads();
    }

    // ---- epilogue: bias + store (float2, 8B aligned) ----
    const int r = l >> 2;
    const int c2 = (l & 3) * 2;
#pragma unroll
    for (int mt = 0; mt < 2; mt++) {
#pragma unroll
        for (int nt = 0; nt < 4; nt++) {
            int lb = n_base + nt * 8 + c2;
            float b0 = bias[lb], b1 = bias[lb + 1];
            size_t m1 = (size_t)(m0 + m_base + mt * 16 + r);
            int g1 = g0 + lb;
            *reinterpret_cast<float2*>(&g_gi[m1 * G3 + g1]) =
                make_float2(d[mt][nt][0] + b0, d[mt][nt][1] + b1);
            *reinterpret_cast<float2*>(&g_gi[(m1 + 8) * G3 + g1]) =
                make_float2(d[mt][nt][2] + b0, d[mt][nt][3] + b1);
        }
    }
}

// =====================================================================
// Kernel 2: persistent GRU scan (round-9 best, unchanged).
// =====================================================================
#define HS_STRIDE 516
#define WS_STRIDE 516
#define RS_STRIDE 530

__global__ void __launch_bounds__(512, 1) gru_scan_kernel(
    const float* __restrict__ hxs,
    const float* __restrict__ masks,
    const float* __restrict__ w_hh,
    const float* __restrict__ b_hh,
    float* __restrict__ out)
{
    extern __shared__ float smem[];
    float* hs  = smem;                                   // [16][516]
    float* ws  = smem + 16 * HS_STRIDE;                  // [48][516] (swizzled)
    float* red = smem + 16 * HS_STRIDE + 48 * WS_STRIDE; // [24][530]

    const int tid = threadIdx.x;
    const int wid = tid >> 5;
    const int jb = blockIdx.x & 31;
    const int rb = blockIdx.x >> 5;
    const int n0 = rb * 16;
    const int ks = tid >> 5;
    const int pos = tid & 31;
    const int rg = pos & 3;
    const int dg = pos >> 2;

    const int e_dim  = tid & 15;
    const int e_rloc = tid >> 4;
    const int e_dimg = jb * 16 + e_dim;
    const int e_i  = (e_rloc >> 2) & 3;
    const int e_rg = e_rloc & 3;
    const int e_dg = e_dim >> 1;
    const int e_dd = e_dim & 1;
    const int e_pcol = e_dg * 4 + e_rg;

#pragma unroll
    for (int i = 0; i < 12; i++) {
        int s = tid + i * 512;
        int lrow = s >> 7;
        int kq = s & 127;
        int g = lrow >> 4;
        int dloc = lrow & 15;
        int sw = (lrow & 8) ? 4 : 0;
        float4 v = *reinterpret_cast<const float4*>(
            &w_hh[(size_t)(g * HH + jb * 16 + dloc) * HH + kq * 4]);
        *reinterpret_cast<float4*>(&ws[lrow * WS_STRIDE + kq * 4 + sw]) = v;
    }
    const float bh_r = (wid < 8) ? b_hh[e_dimg] : 0.f;
    const float bh_z = (wid < 8) ? b_hh[HH + e_dimg] : 0.f;
    const float bh_n = (wid < 8) ? b_hh[2 * HH + e_dimg] : 0.f;

    const ulonglong2* ws_v = reinterpret_cast<const ulonglong2*>(ws);
    const ulonglong2* hs_v = reinterpret_cast<const ulonglong2*>(hs);
    const ulonglong2* hp = hs_v + rg * 129 + ks;
    int woff[6];
#pragma unroll
    for (int c = 0; c < 6; c++) {
        int g = c >> 1, dd = c & 1;
        int lrow = g * 16 + dg * 2 + dd;
        woff[c] = lrow * 129 + ((lrow >> 3) & 1) + ks;
    }

    float hprev_reg = 0.f;

    for (int t = 0; t < TT; t++) {
        float e_m = 0.f, e_ir = 0.f, e_iz = 0.f, e_inn = 0.f;
        int e_mm = 0, e_n = 0;
        if (wid < 8) {
            e_n = n0 + e_rloc;
            e_mm = t * NN + e_n;
            e_m = __ldg(&masks[e_mm]);
            const float* gi = g_gi + (size_t)e_mm * G3;
            e_ir  = __ldg(&gi[e_dimg]);
            e_iz  = __ldg(&gi[HH + e_dimg]);
            e_inn = __ldg(&gi[2 * HH + e_dimg]);
            if (t == 0)
                hprev_reg = hxs[(size_t)e_n * HH + e_dimg];
        } else {
            if (t > 0) {
                if (tid == 256) {
                    const unsigned tgt = 32u * (unsigned)t;
                    unsigned e;
                    do {
                        asm volatile("ld.acquire.gpu.global.u32 %0, [%1];"
                                     : "=r"(e) : "l"(&g_cnt[rb].v) : "memory");
                    } while (e < tgt);
                }
                asm volatile("bar.sync 3, 256;" ::: "memory");
            }
            const float* hsrc = (t == 0) ? hxs : (out + (size_t)(t - 1) * NN * HH);
            const int lt = tid - 256;
#pragma unroll
            for (int i = 0; i < 8; i++) {
                int s = lt + i * 256;
                int row = s >> 7;
                int kq = s & 127;
                float4 v = __ldcg(reinterpret_cast<const float4*>(
                    &hsrc[(size_t)(n0 + row) * HH + kq * 4]));
                *reinterpret_cast<float4*>(&hs[row * HS_STRIDE + kq * 4]) = v;
            }
        }
        __syncthreads();

        ull acc[24];
#pragma unroll
        for (int s = 0; s < 24; s++) acc[s] = 0ull;

#pragma unroll 2
        for (int kk = 0; kk < 8; kk++) {
            const int ko = kk * 16;
            ulonglong2 a2[4];
#pragma unroll
            for (int i = 0; i < 4; i++) a2[i] = hp[i * (4 * 129) + ko];
            ulonglong2 w2[6];
#pragma unroll
            for (int c = 0; c < 6; c++) w2[c] = ws_v[woff[c] + ko];
#pragma unroll
            for (int i = 0; i < 4; i++)
#pragma unroll
                for (int c = 0; c < 6; c++) {
                    acc[i * 6 + c] = fma2(a2[i].x, w2[c].x, acc[i * 6 + c]);
                    acc[i * 6 + c] = fma2(a2[i].y, w2[c].y, acc[i * 6 + c]);
                }
        }

#pragma unroll
        for (int s = 0; s < 24; s++)
            red[s * RS_STRIDE + ks * 33 + pos] = lo32(acc[s]) + hi32(acc[s]);
        __syncthreads();

        if (wid < 8) {
            float pr = 0.f, pz = 0.f, pn = 0.f;
            const int sr = (e_i * 6 + 0 + e_dd) * RS_STRIDE + e_pcol;
            const int sz = (e_i * 6 + 2 + e_dd) * RS_STRIDE + e_pcol;
            const int sn = (e_i * 6 + 4 + e_dd) * RS_STRIDE + e_pcol;
#pragma unroll
            for (int k = 0; k < 16; k++) {
                pr += red[sr + k * 33];
                pz += red[sz + k * 33];
                pn += red[sn + k * 33];
            }
            float ghr = pr * e_m + bh_r;
            float ghz = pz * e_m + bh_z;
            float ghn = pn * e_m + bh_n;

            float r = fsigmoid(e_ir + ghr);
            float z = fsigmoid(e_iz + ghz);
            float nc = ftanh_fast(e_inn + r * ghn);
            float hval = e_m * hprev_reg;
            float hnew = (1.0f - z) * nc + z * hval;
            hprev_reg = hnew;

            out[(size_t)e_mm * HH + e_dimg] = hnew;
            if (t == TT - 1)
                out[(size_t)TT * NN * HH + (size_t)e_n * HH + e_dimg] = hnew;

            asm volatile("bar.sync 2, 256;" ::: "memory");
            if (tid == 0 && t < TT - 1)
                asm volatile("red.release.gpu.global.add.u32 [%0], %1;"
                             :: "l"(&g_cnt[rb].v), "r"(1u) : "memory");
        }
    }
}

// =====================================================================
extern "C" void kernel_launch(void* const* d_in, const int* in_sizes, int n_in,
                              void* d_out, int out_size)
{
    const float* x      = (const float*)d_in[0];
    const float* hxs    = (const float*)d_in[1];
    const float* hxs_1  = (const float*)d_in[2];
    const float* masks  = (const float*)d_in[3];
    const float* w_ih   = (const float*)d_in[4];
    const float* w_hh   = (const float*)d_in[5];
    const float* b_ih   = (const float*)d_in[6];
    const float* b_hh   = (const float*)d_in[7];
    float* out = (float*)d_out;

    // third output: hxs_1 passthrough
    cudaMemcpyAsync(out + (size_t)(TT * NN + NN) * HH, hxs_1,
                    (size_t)NN * HH * sizeof(float), cudaMemcpyDeviceToDevice);

    // tensor-core bf16-split GEMM for gi (also resets scan counters)
    cudaFuncSetAttribute(gemm_mma_kernel,
                         cudaFuncAttributeMaxDynamicSharedMemorySize, GM_SMEM);
    gemm_mma_kernel<<<dim3(G3 / 64, (TT * NN) / 128), 256, GM_SMEM>>>(x, w_ih, b_ih);

    // persistent scan
    size_t shmem = (size_t)(16 * HS_STRIDE + 48 * WS_STRIDE + 24 * RS_STRIDE)
                   * sizeof(float);
    cudaFuncSetAttribute(gru_scan_kernel,
                         cudaFuncAttributeMaxDynamicSharedMemorySize, (int)shmem);
    gru_scan_kernel<<<128, 512, shmem>>>(hxs, masks, w_hh, b_hh, out);
}

// round 12
// speedup vs baseline: 1.8295x; 1.1379x over previous
#include <cuda_runtime.h>
#include <cuda_bf16.h>
#include <cstdint>
#include <math.h>

// Problem dims
#define TT 128
#define NN 64
#define DD 512
#define HH 512
#define G3 1536   // 3*H

typedef unsigned long long ull;

__device__ __forceinline__ float fsigmoid(float x) {
    return 1.0f / (1.0f + __expf(-x));
}
__device__ __forceinline__ float ftanh_fast(float x) {
    float ax = fabsf(x);
    float e = __expf(-2.0f * ax);
    float t = (1.0f - e) / (1.0f + e);
    return copysignf(t, x);
}

// ---------------- mma helpers (baseline PTX, no 'a' features) ----------------
__device__ __forceinline__ uint32_t smem_u32(const void* p) {
    uint32_t a;
    asm("{ .reg .u64 t; cvta.to.shared.u64 t, %1; cvt.u32.u64 %0, t; }" : "=r"(a) : "l"(p));
    return a;
}
__device__ __forceinline__ void ldsm_x4(uint32_t& r0, uint32_t& r1, uint32_t& r2,
                                        uint32_t& r3, uint32_t addr) {
    asm volatile("ldmatrix.sync.aligned.m8n8.x4.shared.b16 {%0,%1,%2,%3}, [%4];"
                 : "=r"(r0), "=r"(r1), "=r"(r2), "=r"(r3) : "r"(addr));
}
__device__ __forceinline__ void mma_bf16(float* d, const uint32_t* a,
                                         uint32_t b0, uint32_t b1) {
    asm volatile("mma.sync.aligned.m16n8k16.row.col.f32.bf16.bf16.f32 "
                 "{%0,%1,%2,%3}, {%4,%5,%6,%7}, {%8,%9}, {%0,%1,%2,%3};"
                 : "+f"(d[0]), "+f"(d[1]), "+f"(d[2]), "+f"(d[3])
                 : "r"(a[0]), "r"(a[1]), "r"(a[2]), "r"(a[3]), "r"(b0), "r"(b1));
}
// split two fp32 into packed bf16 hi pair and lo pair
__device__ __forceinline__ void split2(float a, float b, unsigned& hi, unsigned& lo) {
    __nv_bfloat16 ha = __float2bfloat16(a), hb = __float2bfloat16(b);
    hi = ((unsigned)__bfloat16_as_ushort(hb) << 16) | __bfloat16_as_ushort(ha);
    __nv_bfloat16 la = __float2bfloat16(a - __bfloat162float(ha));
    __nv_bfloat16 lb = __float2bfloat16(b - __bfloat162float(hb));
    lo = ((unsigned)__bfloat16_as_ushort(lb) << 16) | __bfloat16_as_ushort(la);
}

// ---------------- global scratch ----------------
__device__ float g_gi[(size_t)TT * NN * G3];   // gi[m][g]

struct __align__(128) PadU { unsigned v; unsigned pad[31]; };
__device__ PadU g_cnt[4];   // accumulating counter per scan row-group

// =====================================================================
// Kernel 1: tensor-core bf16-split GEMM via mma.sync (round-11, proven).
// =====================================================================
#define BK 64
#define A_STR 72
#define AHI_B 0
#define ALO_B 18432
#define BHI_B 36864
#define BLO_B 46080
#define BIAS_B 55296
#define GM_SMEM (55296 + 256)

__global__ void __launch_bounds__(256, 2) gemm_mma_kernel(
    const float* __restrict__ x,
    const float* __restrict__ w_ih,
    const float* __restrict__ b_ih)
{
    if (blockIdx.x == 0 && blockIdx.y == 0 && threadIdx.x < 4)
        g_cnt[threadIdx.x].v = 0;

    extern __shared__ char sm[];
    const uint32_t sb = smem_u32(sm);
    float* bias = reinterpret_cast<float*>(sm + BIAS_B);

    const int tid = threadIdx.x;
    const int wid = tid >> 5;
    const int l = tid & 31;
    const int g0 = blockIdx.x * 64;
    const int m0 = blockIdx.y * 128;
    const int m_base = (wid & 3) * 32;
    const int n_base = (wid >> 2) * 32;

    if (tid < 64) bias[tid] = b_ih[g0 + tid];

    uint32_t aoff[2], boff[2];
#pragma unroll
    for (int mt = 0; mt < 2; mt++)
        aoff[mt] = ((m_base + mt * 16 + (l & 15)) * A_STR + (l >> 4) * 8) * 2;
#pragma unroll
    for (int p = 0; p < 2; p++)
        boff[p] = ((n_base + p * 16 + (l & 7) + ((l >> 4) & 1) * 8) * A_STR
                   + ((l >> 3) & 1) * 8) * 2;

    float d[2][4][4];
#pragma unroll
    for (int mt = 0; mt < 2; mt++)
#pragma unroll
        for (int nt = 0; nt < 4; nt++)
#pragma unroll
            for (int r = 0; r < 4; r++) d[mt][nt][r] = 0.f;

    for (int kc = 0; kc < DD; kc += BK) {
#pragma unroll
        for (int it = 0; it < 8; it++) {
            int s = tid + it * 256;
            int row = s >> 4, cq = s & 15;
            float4 v = *reinterpret_cast<const float4*>(
                &x[(size_t)(m0 + row) * DD + kc + cq * 4]);
            unsigned h01, l01, h23, l23;
            split2(v.x, v.y, h01, l01);
            split2(v.z, v.w, h23, l23);
            int eo = (row * A_STR + cq * 4) * 2;
            *reinterpret_cast<uint2*>(sm + AHI_B + eo) = make_uint2(h01, h23);
            *reinterpret_cast<uint2*>(sm + ALO_B + eo) = make_uint2(l01, l23);
        }
#pragma unroll
        for (int it = 0; it < 4; it++) {
            int s = tid + it * 256;
            int row = s >> 4, cq = s & 15;
            float4 v = *reinterpret_cast<const float4*>(
                &w_ih[(size_t)(g0 + row) * DD + kc + cq * 4]);
            unsigned h01, l01, h23, l23;
            split2(v.x, v.y, h01, l01);
            split2(v.z, v.w, h23, l23);
            int eo = (row * A_STR + cq * 4) * 2;
            *reinterpret_cast<uint2*>(sm + BHI_B + eo) = make_uint2(h01, h23);
            *reinterpret_cast<uint2*>(sm + BLO_B + eo) = make_uint2(l01, l23);
        }
        __syncthreads();

#pragma unroll
        for (int kk = 0; kk < BK / 16; kk++) {
            const uint32_t ko = kk * 32;
            uint32_t ahi[2][4], alo[2][4], bhi[2][4], blo[2][4];
#pragma unroll
            for (int mt = 0; mt < 2; mt++) {
                ldsm_x4(ahi[mt][0], ahi[mt][1], ahi[mt][2], ahi[mt][3],
                        sb + AHI_B + aoff[mt] + ko);
                ldsm_x4(alo[mt][0], alo[mt][1], alo[mt][2], alo[mt][3],
                        sb + ALO_B + aoff[mt] + ko);
            }
#pragma unroll
            for (int p = 0; p < 2; p++) {
                ldsm_x4(bhi[p][0], bhi[p][1], bhi[p][2], bhi[p][3],
                        sb + BHI_B + boff[p] + ko);
                ldsm_x4(blo[p][0], blo[p][1], blo[p][2], blo[p][3],
                        sb + BLO_B + boff[p] + ko);
            }
#pragma unroll
            for (int mt = 0; mt < 2; mt++)
#pragma unroll
                for (int p = 0; p < 2; p++)
#pragma unroll
                    for (int sub = 0; sub < 2; sub++) {
                        int nt = p * 2 + sub;
                        mma_bf16(d[mt][nt], ahi[mt], bhi[p][sub * 2], bhi[p][sub * 2 + 1]);
                        mma_bf16(d[mt][nt], ahi[mt], blo[p][sub * 2], blo[p][sub * 2 + 1]);
                        mma_bf16(d[mt][nt], alo[mt], bhi[p][sub * 2], bhi[p][sub * 2 + 1]);
                    }
        }
        __syncthreads();
    }

    const int r = l >> 2;
    const int c2 = (l & 3) * 2;
#pragma unroll
    for (int mt = 0; mt < 2; mt++) {
#pragma unroll
        for (int nt = 0; nt < 4; nt++) {
            int lb = n_base + nt * 8 + c2;
            float b0 = bias[lb], b1 = bias[lb + 1];
            size_t m1 = (size_t)(m0 + m_base + mt * 16 + r);
            int g1 = g0 + lb;
            *reinterpret_cast<float2*>(&g_gi[m1 * G3 + g1]) =
                make_float2(d[mt][nt][0] + b0, d[mt][nt][1] + b1);
            *reinterpret_cast<float2*>(&g_gi[(m1 + 8) * G3 + g1]) =
                make_float2(d[mt][nt][2] + b0, d[mt][nt][3] + b1);
        }
    }
}

// =====================================================================
// Kernel 2: persistent GRU scan with HMMA recurrent dot.
// 4 row-groups (rb, 16 rows) x 32 dim-CTAs (jb, 16 dims), 512 threads.
// Each warp (ks = k-slice of 32): 2 k16-iters x 6 n-tiles x 3 split terms
// of mma.m16n8k16 -> full 16x48 partial in d regs. Partials to smem red,
// epilogue (warps 0-7) sums 16 slices + gates. Skeleton = round 9.
// =====================================================================
#define KSTR 520                     // bf16 elems per smem row
#define W_HI_B 0
#define W_LO_B 49920                 // 48*520*2
#define H_HI_B 99840
#define H_LO_B 116480                // +16*520*2
#define RED_B  133120
#define SC_SMEM (133120 + 13056 * 4) // 185,344 B

__global__ void __launch_bounds__(512, 1) gru_scan_kernel(
    const float* __restrict__ hxs,
    const float* __restrict__ masks,
    const float* __restrict__ w_hh,
    const float* __restrict__ b_hh,
    float* __restrict__ out)
{
    extern __shared__ char smc[];
    const uint32_t sb = smem_u32(smc);
    float* red = reinterpret_cast<float*>(smc + RED_B);

    const int tid = threadIdx.x;
    const int wid = tid >> 5;
    const int l = tid & 31;
    const int ks = wid;                  // k-slice 0..15
    const int jb = blockIdx.x & 31;      // dims jb*16 ..
    const int rb = blockIdx.x >> 5;      // rows rb*16 ..
    const int n0 = rb * 16;

    // epilogue mapping (threads 0..255): (row, dim)
    const int e_dim  = tid & 15;
    const int e_rloc = (tid >> 4) & 15;
    const int e_dimg = jb * 16 + e_dim;

    // ---- stage w_hh slice once, split hi/lo: 48 rows x 512 ----
#pragma unroll
    for (int i = 0; i < 12; i++) {
        int s = tid + i * 512;           // 48 rows x 128 float4
        int lrow = s >> 7;
        int kq = s & 127;
        int g = lrow >> 4, dloc = lrow & 15;
        float4 v = *reinterpret_cast<const float4*>(
            &w_hh[(size_t)(g * HH + jb * 16 + dloc) * HH + kq * 4]);
        unsigned h01, l01, h23, l23;
        split2(v.x, v.y, h01, l01);
        split2(v.z, v.w, h23, l23);
        int bo = lrow * (KSTR * 2) + kq * 8;
        *reinterpret_cast<uint2*>(smc + W_HI_B + bo) = make_uint2(h01, h23);
        *reinterpret_cast<uint2*>(smc + W_LO_B + bo) = make_uint2(l01, l23);
    }
    const float bh_r = (wid < 8) ? b_hh[e_dimg] : 0.f;
    const float bh_z = (wid < 8) ? b_hh[HH + e_dimg] : 0.f;
    const float bh_n = (wid < 8) ? b_hh[2 * HH + e_dimg] : 0.f;

    // ldmatrix byte offsets
    const uint32_t a_off = ((uint32_t)((l & 15) * KSTR + (l >> 4) * 8 + ks * 32)) * 2;
    uint32_t b_off[3];
#pragma unroll
    for (int p = 0; p < 3; p++)
        b_off[p] = ((uint32_t)((p * 16 + (l & 7) + ((l >> 4) & 1) * 8) * KSTR
                    + ((l >> 3) & 1) * 8 + ks * 32)) * 2;

    float hprev_reg = 0.f;

    for (int t = 0; t < TT; t++) {
        float e_m = 0.f, e_ir = 0.f, e_iz = 0.f, e_inn = 0.f;
        int e_mm = 0, e_n = 0;
        if (wid < 8) {
            e_n = n0 + e_rloc;
            e_mm = t * NN + e_n;
            e_m = __ldg(&masks[e_mm]);
            const float* gi = g_gi + (size_t)e_mm * G3;
            e_ir  = __ldg(&gi[e_dimg]);
            e_iz  = __ldg(&gi[HH + e_dimg]);
            e_inn = __ldg(&gi[2 * HH + e_dimg]);
            if (t == 0)
                hprev_reg = hxs[(size_t)e_n * HH + e_dimg];
        } else {
            if (t > 0) {
                if (tid == 256) {
                    const unsigned tgt = 32u * (unsigned)t;
                    unsigned e;
                    do {
                        asm volatile("ld.acquire.gpu.global.u32 %0, [%1];"
                                     : "=r"(e) : "l"(&g_cnt[rb].v) : "memory");
                    } while (e < tgt);
                }
                asm volatile("bar.sync 3, 256;" ::: "memory");
            }
            const float* hsrc = (t == 0) ? hxs : (out + (size_t)(t - 1) * NN * HH);
            const int lt = tid - 256;
#pragma unroll
            for (int i = 0; i < 8; i++) {
                int s = lt + i * 256;        // 16 rows x 128 float4
                int row = s >> 7;
                int kq = s & 127;
                float4 v = __ldcg(reinterpret_cast<const float4*>(
                    &hsrc[(size_t)(n0 + row) * HH + kq * 4]));
                unsigned h01, l01, h23, l23;
                split2(v.x, v.y, h01, l01);
                split2(v.z, v.w, h23, l23);
                int bo = row * (KSTR * 2) + kq * 8;
                *reinterpret_cast<uint2*>(smc + H_HI_B + bo) = make_uint2(h01, h23);
                *reinterpret_cast<uint2*>(smc + H_LO_B + bo) = make_uint2(l01, l23);
            }
        }
        __syncthreads();

        // ======= HMMA dot: 16x48 partial for this warp's k-slice =======
        float d[6][4];
#pragma unroll
        for (int nt = 0; nt < 6; nt++)
#pragma unroll
            for (int r = 0; r < 4; r++) d[nt][r] = 0.f;

#pragma unroll
        for (int kk = 0; kk < 2; kk++) {
            const uint32_t ko = kk * 32;     // bytes (16 bf16)
            uint32_t ah[4], al[4];
            ldsm_x4(ah[0], ah[1], ah[2], ah[3], sb + H_HI_B + a_off + ko);
            ldsm_x4(al[0], al[1], al[2], al[3], sb + H_LO_B + a_off + ko);
#pragma unroll
            for (int p = 0; p < 3; p++) {
                uint32_t bh[4], bl[4];
                ldsm_x4(bh[0], bh[1], bh[2], bh[3], sb + W_HI_B + b_off[p] + ko);
                ldsm_x4(bl[0], bl[1], bl[2], bl[3], sb + W_LO_B + b_off[p] + ko);
#pragma unroll
                for (int sub = 0; sub < 2; sub++) {
                    int nt = p * 2 + sub;
                    mma_bf16(d[nt], ah, bh[sub * 2], bh[sub * 2 + 1]);
                    mma_bf16(d[nt], ah, bl[sub * 2], bl[sub * 2 + 1]);
                    mma_bf16(d[nt], al, bh[sub * 2], bh[sub * 2 + 1]);
                }
            }
        }

        // ---- store partials: red[(row*48 + n)*17 + (ks ^ ((row&3)<<2))] ----
#pragma unroll
        for (int nt = 0; nt < 6; nt++)
#pragma unroll
            for (int r = 0; r < 4; r++) {
                int n = nt * 8 + (l & 3) * 2 + (r & 1);
                int row = (l >> 2) + 8 * (r >> 1);
                red[(row * 48 + n) * 17 + (ks ^ ((row & 3) << 2))] = d[nt][r];
            }
        __syncthreads();

        // ======= epilogue (warps 0-7): sum 16 slices, gates, store =======
        if (wid < 8) {
            float p3[3];
#pragma unroll
            for (int g = 0; g < 3; g++) {
                const float* bp = &red[(e_rloc * 48 + g * 16 + e_dim) * 17];
                float s = 0.f;
#pragma unroll
                for (int k = 0; k < 16; k++) s += bp[k];
                p3[g] = s;
            }
            float ghr = p3[0] * e_m + bh_r;
            float ghz = p3[1] * e_m + bh_z;
            float ghn = p3[2] * e_m + bh_n;

            float r = fsigmoid(e_ir + ghr);
            float z = fsigmoid(e_iz + ghz);
            float nc = ftanh_fast(e_inn + r * ghn);
            float hval = e_m * hprev_reg;
            float hnew = (1.0f - z) * nc + z * hval;
            hprev_reg = hnew;

            out[(size_t)e_mm * HH + e_dimg] = hnew;
            if (t == TT - 1)
                out[(size_t)TT * NN * HH + (size_t)e_n * HH + e_dimg] = hnew;

            asm volatile("bar.sync 2, 256;" ::: "memory");
            if (tid == 0 && t < TT - 1)
                asm volatile("red.release.gpu.global.add.u32 [%0], %1;"
                             :: "l"(&g_cnt[rb].v), "r"(1u) : "memory");
        }
        // warps 8-15 fall through to next iteration's poll+stage
    }
}

// =====================================================================
extern "C" void kernel_launch(void* const* d_in, const int* in_sizes, int n_in,
                              void* d_out, int out_size)
{
    const float* x      = (const float*)d_in[0];
    const float* hxs    = (const float*)d_in[1];
    const float* hxs_1  = (const float*)d_in[2];
    const float* masks  = (const float*)d_in[3];
    const float* w_ih   = (const float*)d_in[4];
    const float* w_hh   = (const float*)d_in[5];
    const float* b_ih   = (const float*)d_in[6];
    const float* b_hh   = (const float*)d_in[7];
    float* out = (float*)d_out;

    // third output: hxs_1 passthrough
    cudaMemcpyAsync(out + (size_t)(TT * NN + NN) * HH, hxs_1,
                    (size_t)NN * HH * sizeof(float), cudaMemcpyDeviceToDevice);

    // tensor-core bf16-split GEMM for gi (also resets scan counters)
    cudaFuncSetAttribute(gemm_mma_kernel,
                         cudaFuncAttributeMaxDynamicSharedMemorySize, GM_SMEM);
    gemm_mma_kernel<<<dim3(G3 / 64, (TT * NN) / 128), 256, GM_SMEM>>>(x, w_ih, b_ih);

    // persistent scan (HMMA recurrent dot)
    cudaFuncSetAttribute(gru_scan_kernel,
                         cudaFuncAttributeMaxDynamicSharedMemorySize, SC_SMEM);
    gru_scan_kernel<<<128, 512, SC_SMEM>>>(hxs, masks, w_hh, b_hh, out);
}